// round 1
// baseline (speedup 1.0000x reference)
#include <cuda_runtime.h>
#include <cuda_bf16.h>
#include <math.h>

// Problem: Bahdanau attention
//   hidden [32,1024], encoder [32,2048,1024], W_a [1024,1024], U_a [1024,1024], v_a [1024]
//   wh = hidden @ W^T                         [32,1024]
//   score[b,s] = sum_o v[o]*tanh(wh[b,o] + sum_h U[o,h]*enc[b,s,h])
//   attn = softmax_s(score)                   [32,2048]
//   context[b,h] = sum_s attn[b,s]*enc[b,s,h] [32,1024]
// Output: context (32768 floats) then attn (65536 floats).

#define B_  32
#define S_  2048
#define H_  1024
#define M_  (B_ * S_)          // 65536 tokens
#define NOT 8                  // o-tiles (1024/128)

// Scratch (no allocations allowed)
__device__ float g_wh[B_ * H_];            // 128 KB
__device__ float g_spart[NOT * M_];        // 2 MB: per-o-tile partial scores
__device__ float g_cpart[8 * B_ * H_];     // 1 MB: per-s-chunk partial context

// ---------------------------------------------------------------------------
// Kernel 1: wh[b,o] = sum_h hidden[b,h] * W[o,h]
// ---------------------------------------------------------------------------
__global__ void wh_kernel(const float* __restrict__ hidden,
                          const float* __restrict__ W) {
    int b = blockIdx.x;
    int o = blockIdx.y * 256 + threadIdx.x;
    const float4* h4 = (const float4*)(hidden + b * H_);
    const float4* w4 = (const float4*)(W + o * H_);
    float acc = 0.f;
#pragma unroll 8
    for (int k = 0; k < H_ / 4; k++) {
        float4 hh = h4[k], ww = w4[k];
        acc += hh.x * ww.x + hh.y * ww.y + hh.z * ww.z + hh.w * ww.w;
    }
    g_wh[b * H_ + o] = acc;
}

// ---------------------------------------------------------------------------
// Kernel 2: fused score GEMM.  Tile: BM=128 tokens x BN=128 o, BK=16.
// 256 threads, 8x8 accum per thread. Epilogue: tanh, dot with v, reduce
// across the 16 o-lanes, write per-o-tile partial (deterministic, no atomics).
// grid = (8 o-tiles [fast, for L2 reuse of E tile], 512 token-tiles)
// ---------------------------------------------------------------------------
__global__ __launch_bounds__(256, 2)
void score_kernel(const float* __restrict__ E,
                  const float* __restrict__ U,
                  const float* __restrict__ v) {
    __shared__ float Es[16][128];
    __shared__ float Us[16][128];

    const int t  = threadIdx.x;
    const int m0 = blockIdx.y * 128;
    const int o0 = blockIdx.x * 128;
    const int b  = m0 >> 11;            // token tile never crosses batch (2048 % 128 == 0)
    const int tx = t & 15;              // o groups of 8
    const int ty = t >> 4;              // token groups of 8

    float acc[8][8];
#pragma unroll
    for (int i = 0; i < 8; i++)
#pragma unroll
        for (int j = 0; j < 8; j++) acc[i][j] = 0.f;

    for (int k0 = 0; k0 < H_; k0 += 16) {
#pragma unroll
        for (int i = 0; i < 2; i++) {
            int id = i * 256 + t;
            int row = id >> 2, quad = id & 3;
            float4 e = *(const float4*)&E[(m0 + row) * H_ + k0 + quad * 4];
            Es[quad * 4 + 0][row] = e.x; Es[quad * 4 + 1][row] = e.y;
            Es[quad * 4 + 2][row] = e.z; Es[quad * 4 + 3][row] = e.w;
            float4 u = *(const float4*)&U[(o0 + row) * H_ + k0 + quad * 4];
            Us[quad * 4 + 0][row] = u.x; Us[quad * 4 + 1][row] = u.y;
            Us[quad * 4 + 2][row] = u.z; Us[quad * 4 + 3][row] = u.w;
        }
        __syncthreads();
#pragma unroll
        for (int kk = 0; kk < 16; kk++) {
            float a[8], bb[8];
            *(float4*)(a)      = *(const float4*)&Es[kk][ty * 8];
            *(float4*)(a + 4)  = *(const float4*)&Es[kk][ty * 8 + 4];
            *(float4*)(bb)     = *(const float4*)&Us[kk][tx * 8];
            *(float4*)(bb + 4) = *(const float4*)&Us[kk][tx * 8 + 4];
#pragma unroll
            for (int i = 0; i < 8; i++)
#pragma unroll
                for (int j = 0; j < 8; j++) acc[i][j] += a[i] * bb[j];
        }
        __syncthreads();
    }

    // epilogue: score partial for this o-tile
    float vv[8], ww[8];
#pragma unroll
    for (int j = 0; j < 8; j++) {
        int o = o0 + tx * 8 + j;
        vv[j] = v[o];
        ww[j] = g_wh[b * H_ + o];
    }
#pragma unroll
    for (int i = 0; i < 8; i++) {
        float p = 0.f;
#pragma unroll
        for (int j = 0; j < 8; j++)
            p += vv[j] * tanhf(acc[i][j] + ww[j]);
        // reduce across 16 o-lanes (tx lives in low 4 bits of lane id)
        p += __shfl_xor_sync(0xffffffffu, p, 8);
        p += __shfl_xor_sync(0xffffffffu, p, 4);
        p += __shfl_xor_sync(0xffffffffu, p, 2);
        p += __shfl_xor_sync(0xffffffffu, p, 1);
        if (tx == 0)
            g_spart[blockIdx.x * M_ + m0 + ty * 8 + i] = p;
    }
}

// ---------------------------------------------------------------------------
// Kernel 3: per-batch softmax over S=2048 (sums the 8 o-tile partials first).
// Writes attn into d_out[32768 ..].
// ---------------------------------------------------------------------------
__global__ void softmax_kernel(float* __restrict__ out) {
    __shared__ float buf[S_];
    __shared__ float red[256];
    const int b = blockIdx.x, t = threadIdx.x;

    float mx = -1e30f;
    for (int s = t; s < S_; s += 256) {
        float sc = 0.f;
#pragma unroll
        for (int p = 0; p < NOT; p++) sc += g_spart[p * M_ + b * S_ + s];
        buf[s] = sc;
        mx = fmaxf(mx, sc);
    }
    red[t] = mx; __syncthreads();
    for (int o = 128; o > 0; o >>= 1) {
        if (t < o) red[t] = fmaxf(red[t], red[t + o]);
        __syncthreads();
    }
    mx = red[0]; __syncthreads();

    float sum = 0.f;
    for (int s = t; s < S_; s += 256) {
        float e = __expf(buf[s] - mx);
        buf[s] = e;
        sum += e;
    }
    red[t] = sum; __syncthreads();
    for (int o = 128; o > 0; o >>= 1) {
        if (t < o) red[t] += red[t + o];
        __syncthreads();
    }
    float inv = 1.0f / red[0];

    float* attn = out + B_ * H_;
    for (int s = t; s < S_; s += 256)
        attn[b * S_ + s] = buf[s] * inv;
}

// ---------------------------------------------------------------------------
// Kernel 4: context partials. grid=(8 s-chunks, 32 b); each block covers all
// 1024 h (256 threads x float4), sums 256 s values.
// ---------------------------------------------------------------------------
__global__ void ctx_part_kernel(const float* __restrict__ E,
                                const float* __restrict__ out) {
    __shared__ float a[256];
    const int sc = blockIdx.x, b = blockIdx.y, t = threadIdx.x;
    const float* attn = out + B_ * H_;
    a[t] = attn[b * S_ + sc * 256 + t];
    __syncthreads();

    const float4* E4 = (const float4*)E;
    float4 acc = make_float4(0.f, 0.f, 0.f, 0.f);
    int base = (b * S_ + sc * 256) * (H_ / 4) + t;
#pragma unroll 4
    for (int s = 0; s < 256; s++) {
        float w = a[s];
        float4 e = E4[base + s * (H_ / 4)];
        acc.x += w * e.x; acc.y += w * e.y;
        acc.z += w * e.z; acc.w += w * e.w;
    }
    ((float4*)g_cpart)[(sc * B_ + b) * (H_ / 4) + t] = acc;
}

// ---------------------------------------------------------------------------
// Kernel 5: reduce 8 context partials -> d_out[0 .. 32767]
// ---------------------------------------------------------------------------
__global__ void ctx_reduce_kernel(float* __restrict__ out) {
    int i = blockIdx.x * 256 + threadIdx.x;   // 0..32767 = b*1024 + h
    float s = 0.f;
#pragma unroll
    for (int p = 0; p < 8; p++) s += g_cpart[p * (B_ * H_) + i];
    out[i] = s;
}

// ---------------------------------------------------------------------------
extern "C" void kernel_launch(void* const* d_in, const int* in_sizes, int n_in,
                              void* d_out, int out_size) {
    const float* hidden = (const float*)d_in[0];
    const float* E      = (const float*)d_in[1];
    const float* W      = (const float*)d_in[2];
    const float* U      = (const float*)d_in[3];
    const float* v      = (const float*)d_in[4];
    float* out = (float*)d_out;

    wh_kernel<<<dim3(32, 4), 256>>>(hidden, W);
    score_kernel<<<dim3(NOT, M_ / 128), 256>>>(E, U, v);
    softmax_kernel<<<B_, 256>>>(out);
    ctx_part_kernel<<<dim3(8, B_), 256>>>(E, out);
    ctx_reduce_kernel<<<(B_ * H_) / 256, 256>>>(out);
}

// round 4
// speedup vs baseline: 2.1816x; 2.1816x over previous
#include <cuda_runtime.h>
#include <cuda_bf16.h>
#include <math.h>
#include <stdint.h>

// Bahdanau attention, B=32 S=2048 H=1024.
//   wh = hidden @ W^T
//   score[b,s] = sum_o v[o]*tanh(wh[b,o] + sum_h U[o,h]*enc[b,s,h])
//       score GEMM via warp mma.sync bf16 with 3-term split (fp32-quality)
//   attn = softmax_s(score); context = attn @ enc
// Output: context (32768 f32) then attn (65536 f32).

#define B_  32
#define S_  2048
#define H_  1024
#define M_  (B_ * S_)
#define NOT 8                      // o-tiles of 128

__device__ float g_wh[B_ * H_];
__device__ float g_spart[NOT * M_];
__device__ float g_cpart[8 * B_ * H_];

// ---------------------------------------------------------------------------
// mma.sync m16n8k16 row.col f32.bf16.bf16.f32, D += A*B
// ---------------------------------------------------------------------------
#define MMA16816(d, a, b) \
    asm volatile("mma.sync.aligned.m16n8k16.row.col.f32.bf16.bf16.f32 " \
        "{%0,%1,%2,%3}, {%4,%5,%6,%7}, {%8,%9}, {%0,%1,%2,%3};" \
        : "+f"((d)[0]), "+f"((d)[1]), "+f"((d)[2]), "+f"((d)[3]) \
        : "r"((a)[0]), "r"((a)[1]), "r"((a)[2]), "r"((a)[3]), \
          "r"((b)[0]), "r"((b)[1]))

// ---------------------------------------------------------------------------
// FMA-only fast tanh (rational 13/6 + bit-hack Newton reciprocal). No MUFU.
// ---------------------------------------------------------------------------
__device__ __forceinline__ float fast_tanh(float x) {
    float xc = fminf(fmaxf(x, -7.90531110763549805f), 7.90531110763549805f);
    float x2 = xc * xc;
    float p = -2.76076847742355e-16f;
    p = fmaf(p, x2, 2.00018790482477e-13f);
    p = fmaf(p, x2, -8.60467152213735e-11f);
    p = fmaf(p, x2, 5.12229709037114e-08f);
    p = fmaf(p, x2, 1.48572235717979e-05f);
    p = fmaf(p, x2, 6.37261928875436e-04f);
    p = fmaf(p, x2, 4.89352455891786e-03f);
    p = p * xc;
    float q = 1.19825839466702e-06f;
    q = fmaf(q, x2, 1.18534705686654e-04f);
    q = fmaf(q, x2, 2.26843463243900e-03f);
    q = fmaf(q, x2, 4.89352518554385e-03f);
    float r = __int_as_float(0x7EF311C3 - __float_as_int(q));
    r = r * fmaf(-q, r, 2.0f);
    r = r * fmaf(-q, r, 2.0f);
    return p * r;
}

// ---------------------------------------------------------------------------
// Kernel 1: wh[b,o] = sum_h hidden[b,h] * W[o,h]
// ---------------------------------------------------------------------------
__global__ void wh_kernel(const float* __restrict__ hidden,
                          const float* __restrict__ W) {
    int b = blockIdx.x;
    int o = blockIdx.y * 256 + threadIdx.x;
    const float4* h4 = (const float4*)(hidden + b * H_);
    const float4* w4 = (const float4*)(W + (size_t)o * H_);
    float acc = 0.f;
#pragma unroll 8
    for (int k = 0; k < H_ / 4; k++) {
        float4 hh = h4[k], ww = w4[k];
        acc += hh.x * ww.x + hh.y * ww.y + hh.z * ww.z + hh.w * ww.w;
    }
    g_wh[b * H_ + o] = acc;
}

// ---------------------------------------------------------------------------
// Kernel 2: score GEMM via mma.sync. Tile 128(tokens) x 128(o) x BK=32.
// 8 warps: 4 m-warps (32 rows) x 2 n-warps (64 cols); warp = 2 mfrag x 8 nfrag.
// Split bf16: ue = Ehi*Uhi + Ehi*Ulo + Elo*Uhi  (3 HMMA per frag pair).
// SMEM rows padded to 80B -> all fragment lds.u32 are bank-conflict-free.
// Epilogue: tanh(acc+wh)*v, quad+block reduce -> per-o-tile partial scores.
// ---------------------------------------------------------------------------
#define BK      32
#define RSTR    80                 // smem row stride bytes (32 bf16 = 64B + 16 pad)
#define SM_EH   0
#define SM_EL   10240
#define SM_UH   20480
#define SM_UL   30720
#define SM_VW   40960              // float2[128]  (v, wh)
#define SM_SRED 41984              // float[128][2]
#define SM_SZ   43008

__device__ __forceinline__ void split_store(char* base_hi, char* base_lo,
                                            int row, int q, float4 x) {
    __nv_bfloat16 h0 = __float2bfloat16_rn(x.x);
    __nv_bfloat16 h1 = __float2bfloat16_rn(x.y);
    __nv_bfloat16 h2 = __float2bfloat16_rn(x.z);
    __nv_bfloat16 h3 = __float2bfloat16_rn(x.w);
    __nv_bfloat16 l0 = __float2bfloat16_rn(x.x - __bfloat162float(h0));
    __nv_bfloat16 l1 = __float2bfloat16_rn(x.y - __bfloat162float(h1));
    __nv_bfloat16 l2 = __float2bfloat16_rn(x.z - __bfloat162float(h2));
    __nv_bfloat16 l3 = __float2bfloat16_rn(x.w - __bfloat162float(h3));
    uint2 Hh, Ll;
    Hh.x = (uint32_t)__bfloat16_as_ushort(h0) | ((uint32_t)__bfloat16_as_ushort(h1) << 16);
    Hh.y = (uint32_t)__bfloat16_as_ushort(h2) | ((uint32_t)__bfloat16_as_ushort(h3) << 16);
    Ll.x = (uint32_t)__bfloat16_as_ushort(l0) | ((uint32_t)__bfloat16_as_ushort(l1) << 16);
    Ll.y = (uint32_t)__bfloat16_as_ushort(l2) | ((uint32_t)__bfloat16_as_ushort(l3) << 16);
    *(uint2*)(base_hi + row * RSTR + q * 8) = Hh;
    *(uint2*)(base_lo + row * RSTR + q * 8) = Ll;
}

__global__ __launch_bounds__(256, 2)
void score_mma_kernel(const float* __restrict__ E,
                      const float* __restrict__ U,
                      const float* __restrict__ v) {
    __shared__ __align__(16) char smem[SM_SZ];

    const int t    = threadIdx.x;
    const int wid  = t >> 5;
    const int lane = t & 31;
    const int q    = lane & 3;          // quad id
    const int r    = lane >> 2;         // 0..7
    const int wm   = (wid & 3) * 32;    // warp m offset
    const int wn   = (wid >> 2) * 64;   // warp n offset
    const int wni  = wid >> 2;
    const int o0   = blockIdx.x * 128;
    const int m0   = blockIdx.y * 128;
    const int b    = m0 >> 11;          // token tile never crosses batch

    // (v, wh) for this o-tile
    if (t < 128) {
        float2* vw = (float2*)(smem + SM_VW);
        vw[t] = make_float2(v[o0 + t], g_wh[b * H_ + o0 + t]);
    }

    float cacc[2][8][4];
#pragma unroll
    for (int mf = 0; mf < 2; mf++)
#pragma unroll
        for (int nf = 0; nf < 8; nf++)
#pragma unroll
            for (int d = 0; d < 4; d++) cacc[mf][nf][d] = 0.f;

    const int lrow = t >> 3;            // 0..31
    const int lq   = t & 7;             // col quad (float4 index)

#pragma unroll 1
    for (int c = 0; c < H_ / BK; c++) {
        const int k0 = c * BK;
        __syncthreads();                // protect smem from previous iteration
        // E chunk 128x32 and U chunk 128x32, fp32 -> split bf16
#pragma unroll
        for (int i = 0; i < 4; i++) {
            int row = lrow + i * 32;
            float4 xe = *(const float4*)&E[(size_t)(m0 + row) * H_ + k0 + lq * 4];
            split_store(smem + SM_EH, smem + SM_EL, row, lq, xe);
            float4 xu = *(const float4*)&U[(size_t)(o0 + row) * H_ + k0 + lq * 4];
            split_store(smem + SM_UH, smem + SM_UL, row, lq, xu);
        }
        __syncthreads();

#pragma unroll
        for (int kk = 0; kk < 2; kk++) {
            const int kb = kk * 32 + q * 4;   // byte offset of k pair in row
            // A fragments: [hi/lo][a0..a3]
            uint32_t a[2][2][4];
#pragma unroll
            for (int mf = 0; mf < 2; mf++) {
                int rbase = (wm + mf * 16 + r) * RSTR + kb;
#pragma unroll
                for (int s = 0; s < 2; s++) {
                    const char* bp = smem + (s ? SM_EL : SM_EH);
                    a[mf][s][0] = *(const uint32_t*)(bp + rbase);
                    a[mf][s][1] = *(const uint32_t*)(bp + rbase + 8 * RSTR);
                    a[mf][s][2] = *(const uint32_t*)(bp + rbase + 16);
                    a[mf][s][3] = *(const uint32_t*)(bp + rbase + 8 * RSTR + 16);
                }
            }
#pragma unroll
            for (int nf = 0; nf < 8; nf++) {
                int nbase = (wn + nf * 8 + r) * RSTR + kb;
                uint32_t bh[2], bl[2];
                bh[0] = *(const uint32_t*)(smem + SM_UH + nbase);
                bh[1] = *(const uint32_t*)(smem + SM_UH + nbase + 16);
                bl[0] = *(const uint32_t*)(smem + SM_UL + nbase);
                bl[1] = *(const uint32_t*)(smem + SM_UL + nbase + 16);
#pragma unroll
                for (int mf = 0; mf < 2; mf++) {
                    MMA16816(cacc[mf][nf], a[mf][0], bh);   // hi*hi
                    MMA16816(cacc[mf][nf], a[mf][0], bl);   // hi*lo
                    MMA16816(cacc[mf][nf], a[mf][1], bh);   // lo*hi
                }
            }
        }
    }

    // Epilogue: p_row = sum_cols v[col]*tanh(acc + wh[col])
    const float2* vw = (const float2*)(smem + SM_VW);
    float pr[2][2] = {{0.f, 0.f}, {0.f, 0.f}};
#pragma unroll
    for (int mf = 0; mf < 2; mf++)
#pragma unroll
        for (int nf = 0; nf < 8; nf++)
#pragma unroll
            for (int d = 0; d < 4; d++) {
                int col = wn + nf * 8 + 2 * q + (d & 1);
                float2 w = vw[col];
                pr[mf][d >> 1] += w.x * fast_tanh(cacc[mf][nf][d] + w.y);
            }
    // reduce over the 4 quad lanes (cols)
#pragma unroll
    for (int mf = 0; mf < 2; mf++)
#pragma unroll
        for (int h = 0; h < 2; h++) {
            float p = pr[mf][h];
            p += __shfl_xor_sync(0xffffffffu, p, 1);
            p += __shfl_xor_sync(0xffffffffu, p, 2);
            pr[mf][h] = p;
        }
    __syncthreads();
    float* sred = (float*)(smem + SM_SRED);
    if (q == 0) {
#pragma unroll
        for (int mf = 0; mf < 2; mf++)
#pragma unroll
            for (int h = 0; h < 2; h++) {
                int row = wm + mf * 16 + h * 8 + r;
                sred[row * 2 + wni] = pr[mf][h];
            }
    }
    __syncthreads();
    if (t < 128)
        g_spart[(size_t)blockIdx.x * M_ + m0 + t] = sred[t * 2] + sred[t * 2 + 1];
}

// ---------------------------------------------------------------------------
// Kernel 3: per-batch softmax (sums the 8 o-tile partials first).
// ---------------------------------------------------------------------------
__global__ void softmax_kernel(float* __restrict__ out) {
    __shared__ float buf[S_];
    __shared__ float red[256];
    const int b = blockIdx.x, t = threadIdx.x;

    float mx = -1e30f;
    for (int s = t; s < S_; s += 256) {
        float sc = 0.f;
#pragma unroll
        for (int p = 0; p < NOT; p++) sc += g_spart[(size_t)p * M_ + b * S_ + s];
        buf[s] = sc;
        mx = fmaxf(mx, sc);
    }
    red[t] = mx; __syncthreads();
    for (int o = 128; o > 0; o >>= 1) {
        if (t < o) red[t] = fmaxf(red[t], red[t + o]);
        __syncthreads();
    }
    mx = red[0]; __syncthreads();

    float sum = 0.f;
    for (int s = t; s < S_; s += 256) {
        float e = __expf(buf[s] - mx);
        buf[s] = e;
        sum += e;
    }
    red[t] = sum; __syncthreads();
    for (int o = 128; o > 0; o >>= 1) {
        if (t < o) red[t] += red[t + o];
        __syncthreads();
    }
    float inv = 1.0f / red[0];

    float* attn = out + B_ * H_;
    for (int s = t; s < S_; s += 256)
        attn[b * S_ + s] = buf[s] * inv;
}

// ---------------------------------------------------------------------------
// Kernel 4: context partials (8 s-chunks x 32 b), then Kernel 5 reduce.
// ---------------------------------------------------------------------------
__global__ void ctx_part_kernel(const float* __restrict__ E,
                                const float* __restrict__ out) {
    __shared__ float a[256];
    const int sc = blockIdx.x, b = blockIdx.y, t = threadIdx.x;
    const float* attn = out + B_ * H_;
    a[t] = attn[b * S_ + sc * 256 + t];
    __syncthreads();

    const float4* E4 = (const float4*)E;
    float4 acc = make_float4(0.f, 0.f, 0.f, 0.f);
    int base = (b * S_ + sc * 256) * (H_ / 4) + t;
#pragma unroll 4
    for (int s = 0; s < 256; s++) {
        float w = a[s];
        float4 e = E4[base + s * (H_ / 4)];
        acc.x += w * e.x; acc.y += w * e.y;
        acc.z += w * e.z; acc.w += w * e.w;
    }
    ((float4*)g_cpart)[(sc * B_ + b) * (H_ / 4) + t] = acc;
}

__global__ void ctx_reduce_kernel(float* __restrict__ out) {
    int i = blockIdx.x * 256 + threadIdx.x;
    float s = 0.f;
#pragma unroll
    for (int p = 0; p < 8; p++) s += g_cpart[p * (B_ * H_) + i];
    out[i] = s;
}

// ---------------------------------------------------------------------------
extern "C" void kernel_launch(void* const* d_in, const int* in_sizes, int n_in,
                              void* d_out, int out_size) {
    const float* hidden = (const float*)d_in[0];
    const float* E      = (const float*)d_in[1];
    const float* W      = (const float*)d_in[2];
    const float* U      = (const float*)d_in[3];
    const float* v      = (const float*)d_in[4];
    float* out = (float*)d_out;

    wh_kernel<<<dim3(32, 4), 256>>>(hidden, W);
    score_mma_kernel<<<dim3(NOT, M_ / 128), 256>>>(E, U, v);
    softmax_kernel<<<B_, 256>>>(out);
    ctx_part_kernel<<<dim3(8, B_), 256>>>(E, out);
    ctx_reduce_kernel<<<(B_ * H_) / 256, 256>>>(out);
}